// round 9
// baseline (speedup 1.0000x reference)
#include <cuda_runtime.h>
#include <cuda_bf16.h>
#include <cstdint>

#define B_ROWS 8192
#define F_DIM 128
#define Q_DIM 64
#define IN_DIM 193
#define H1D 256
#define H2D 256
#define THRESH 0.95f
#define EPSV 1e-12f

#define KT 768   // 3 segments of 256 cols

// Scratch (no allocations allowed)
__device__ __align__(16) __nv_bfloat16 g_xnb[B_ROWS * F_DIM];
__device__ int   g_cnt[B_ROWS];
__device__ __align__(16) __nv_bfloat16 g_fpp[B_ROWS * KT];   // [fh|fh|fl]
__device__ __align__(16) __nv_bfloat16 g_w1pp[H1D * KT];     // [wh|wl|wh]
__device__ __align__(16) __nv_bfloat16 g_hpp[B_ROWS * KT];   // [hh|hh|hl]
__device__ __align__(16) __nv_bfloat16 g_w2pp[H2D * KT];     // [wh|wl|wh]
__device__ __align__(16) float g_h2[B_ROWS * H2D];

__device__ __forceinline__ uint32_t smem_u32(const void* p) {
    uint32_t a;
    asm("{ .reg .u64 t; cvta.to.shared.u64 t, %1; cvt.u32.u64 %0, t; }" : "=r"(a) : "l"(p));
    return a;
}
#define SWZ256(b) ((b) ^ ((((b) >> 8) & 7) << 4))

// ---------------------------------------------------------------------------
// Kernel 1: row L2 norm -> bf16 normalized rows; zero counters
// ---------------------------------------------------------------------------
__global__ void rownorm_kernel(const float* __restrict__ x) {
    int row  = blockIdx.x * 8 + (threadIdx.x >> 5);
    int lane = threadIdx.x & 31;
    const float4* xr = (const float4*)(x + (size_t)row * F_DIM);
    float4 v = xr[lane];
    float s = v.x * v.x + v.y * v.y + v.z * v.z + v.w * v.w;
    #pragma unroll
    for (int o = 16; o > 0; o >>= 1) s += __shfl_xor_sync(0xffffffffu, s, o);
    float inv = 1.0f / (sqrtf(s) + EPSV);
    __nv_bfloat162* outp = (__nv_bfloat162*)(g_xnb + (size_t)row * F_DIM);
    outp[lane * 2 + 0] = __nv_bfloat162(__float2bfloat16_rn(v.x * inv), __float2bfloat16_rn(v.y * inv));
    outp[lane * 2 + 1] = __nv_bfloat162(__float2bfloat16_rn(v.z * inv), __float2bfloat16_rn(v.w * inv));
    if (lane == 0) g_cnt[row] = 0;
}

// ---------------------------------------------------------------------------
// Kernel 2: symmetric gram-count (HMMA). Upper-triangle tiles only. (proven)
// ---------------------------------------------------------------------------
#define GRAM_SMEM_DYN 65536

__global__ void __launch_bounds__(256) gram_mma_kernel() {
    int bi = blockIdx.y, bj = blockIdx.x;
    if (bj < bi) return;
    const bool diag = (bi == bj);

    extern __shared__ char smem[];
    int t = threadIdx.x, wid = t >> 5, lane = t & 31;
    int warp_m = wid >> 2, warp_n = wid & 3;
    int rowBase = bi * 128;
    int colBase = bj * 128;

    uint32_t sA = smem_u32(smem);
    uint32_t sB = sA + 32768;

    #pragma unroll
    for (int l = 0; l < 8; l++) {
        int u = t + l * 256;
        int row = u >> 4, seg = u & 15;
        uint4 va = ((const uint4*)(g_xnb + (size_t)(rowBase + row) * F_DIM))[seg];
        uint4 vb = ((const uint4*)(g_xnb + (size_t)(colBase + row) * F_DIM))[seg];
        uint32_t off = SWZ256((uint32_t)row * 256 + seg * 16);
        *(uint4*)(smem + off)         = va;
        *(uint4*)(smem + 32768 + off) = vb;
    }
    __syncthreads();

    int a_row_l   = warp_m * 64 + (lane & 15);
    int a_chunk_l = lane >> 4;
    int b_row_l   = warp_n * 32 + ((lane >> 4) << 3) + (lane & 7);
    int b_chunk_l = (lane >> 3) & 1;

    float acc[4][4][4];
    #pragma unroll
    for (int mi = 0; mi < 4; mi++)
        #pragma unroll
        for (int ni = 0; ni < 4; ni++)
            #pragma unroll
            for (int r = 0; r < 4; r++) acc[mi][ni][r] = 0.0f;

    #pragma unroll
    for (int kk = 0; kk < 8; kk++) {
        uint32_t a[4][4];
        #pragma unroll
        for (int mi = 0; mi < 4; mi++) {
            uint32_t byte = (uint32_t)(a_row_l + mi * 16) * 256 + (kk * 2 + a_chunk_l) * 16;
            uint32_t addr = sA + SWZ256(byte);
            asm volatile("ldmatrix.sync.aligned.m8n8.x4.shared.b16 {%0,%1,%2,%3}, [%4];"
                         : "=r"(a[mi][0]), "=r"(a[mi][1]), "=r"(a[mi][2]), "=r"(a[mi][3])
                         : "r"(addr));
        }
        uint32_t b[4][2];
        #pragma unroll
        for (int np = 0; np < 2; np++) {
            uint32_t byte = (uint32_t)(b_row_l + np * 16) * 256 + (kk * 2 + b_chunk_l) * 16;
            uint32_t addr = sB + SWZ256(byte);
            asm volatile("ldmatrix.sync.aligned.m8n8.x4.shared.b16 {%0,%1,%2,%3}, [%4];"
                         : "=r"(b[np*2][0]), "=r"(b[np*2][1]), "=r"(b[np*2+1][0]), "=r"(b[np*2+1][1])
                         : "r"(addr));
        }
        #pragma unroll
        for (int mi = 0; mi < 4; mi++)
            #pragma unroll
            for (int ni = 0; ni < 4; ni++)
                asm volatile(
                    "mma.sync.aligned.m16n8k16.row.col.f32.bf16.bf16.f32 "
                    "{%0,%1,%2,%3}, {%4,%5,%6,%7}, {%8,%9}, {%0,%1,%2,%3};"
                    : "+f"(acc[mi][ni][0]), "+f"(acc[mi][ni][1]),
                      "+f"(acc[mi][ni][2]), "+f"(acc[mi][ni][3])
                    : "r"(a[mi][0]), "r"(a[mi][1]), "r"(a[mi][2]), "r"(a[mi][3]),
                      "r"(b[ni][0]), "r"(b[ni][1]));
    }

    int g0 = lane >> 2, q4 = lane & 3;
    #pragma unroll
    for (int mi = 0; mi < 4; mi++) {
        int row0 = rowBase + warp_m * 64 + mi * 16 + g0;
        int row1 = row0 + 8;
        #pragma unroll
        for (int ni = 0; ni < 4; ni++) {
            int c0 = colBase + warp_n * 32 + ni * 8 + q4 * 2;
            #pragma unroll
            for (int r = 0; r < 4; r++) {
                int row = (r < 2) ? row0 : row1;
                int col = c0 + (r & 1);
                float v = acc[mi][ni][r];
                if (v * v >= THRESH && row != col) {
                    atomicAdd(&g_cnt[row], 1);
                    if (!diag) atomicAdd(&g_cnt[col], 1);
                }
            }
        }
    }
}

// ---------------------------------------------------------------------------
// Prep: split-bf16 buffers (all writes to device globals, referenced directly).
// A-side segments [hi|hi|lo]; W-side segments [hi|lo|hi].
// ---------------------------------------------------------------------------
__global__ void prep_feats_kernel(const float* __restrict__ x,
                                  const float* __restrict__ q) {
    int row = blockIdx.x;
    int k = threadIdx.x;                         // 0..255
    float f = 0.0f;
    if (k < F_DIM)               f = x[(size_t)row * F_DIM + k];
    else if (k < F_DIM + Q_DIM)  f = q[(size_t)row * Q_DIM + (k - F_DIM)];
    else if (k == IN_DIM - 1)    f = (float)g_cnt[row] * (1.0f / (float)B_ROWS);
    __nv_bfloat16 hi = __float2bfloat16_rn(f);
    __nv_bfloat16 lo = __float2bfloat16_rn(f - __bfloat162float(hi));
    size_t base = (size_t)row * KT;
    g_fpp[base + k]       = hi;
    g_fpp[base + 256 + k] = hi;
    g_fpp[base + 512 + k] = lo;
}

__global__ void prep_w_kernel(const float* __restrict__ W1,
                              const float* __restrict__ W2) {
    int n = blockIdx.x;                          // 0..255
    int k = threadIdx.x;                         // 0..255
    {
        float f = (k < IN_DIM) ? W1[(size_t)n * IN_DIM + k] : 0.0f;
        __nv_bfloat16 hi = __float2bfloat16_rn(f);
        __nv_bfloat16 lo = __float2bfloat16_rn(f - __bfloat162float(hi));
        size_t base = (size_t)n * KT;
        g_w1pp[base + k]       = hi;
        g_w1pp[base + 256 + k] = lo;
        g_w1pp[base + 512 + k] = hi;
    }
    {
        float f = W2[(size_t)n * H1D + k];
        __nv_bfloat16 hi = __float2bfloat16_rn(f);
        __nv_bfloat16 lo = __float2bfloat16_rn(f - __bfloat162float(hi));
        size_t base = (size_t)n * KT;
        g_w2pp[base + k]       = hi;
        g_w2pp[base + 256 + k] = lo;
        g_w2pp[base + 512 + k] = hi;
    }
}

// ---------------------------------------------------------------------------
// MLP GEMM (HMMA): K=768 in 6 chunks of 128 cols. A/W are device globals
// selected by MODE *inside device code* (NOT passed as host-side args — that
// was the R5/R7 bug: host address of __device__ symbols).
// MODE 0: A=g_fpp, W=g_w1pp, +b1, relu, split -> g_hpp.
// MODE 1: A=g_hpp, W=g_w2pp, +b2, relu -> g_h2 (f32).
// ---------------------------------------------------------------------------
#define MLP_SMEM_DYN 65536

template <int MODE>
__global__ void __launch_bounds__(256) mlp_mma_kernel(const float* __restrict__ bias) {
    const __nv_bfloat16* A = (MODE == 0) ? g_fpp  : g_hpp;
    const __nv_bfloat16* W = (MODE == 0) ? g_w1pp : g_w2pp;

    extern __shared__ char smem[];
    int t = threadIdx.x, wid = t >> 5, lane = t & 31;
    int warp_m = wid >> 2, warp_n = wid & 3;
    int mBase = blockIdx.y * 128;
    int nBase = blockIdx.x * 128;

    uint32_t sA = smem_u32(smem);
    uint32_t sB = sA + 32768;

    int a_row_l   = warp_m * 64 + (lane & 15);
    int a_chunk_l = lane >> 4;
    int b_row_l   = warp_n * 32 + ((lane >> 4) << 3) + (lane & 7);
    int b_chunk_l = (lane >> 3) & 1;

    float acc[4][4][4];
    #pragma unroll
    for (int mi = 0; mi < 4; mi++)
        #pragma unroll
        for (int ni = 0; ni < 4; ni++)
            #pragma unroll
            for (int r = 0; r < 4; r++) acc[mi][ni][r] = 0.0f;

    for (int c = 0; c < KT / 128; c++) {
        if (c) __syncthreads();                  // previous chunk fully consumed
        #pragma unroll
        for (int l = 0; l < 8; l++) {
            int u = t + l * 256;
            int row = u >> 4, seg = u & 15;
            // rows are KT bf16 = 1536B; take this chunk's 256B slice
            const char* pa = (const char*)A + (size_t)(mBase + row) * (KT * 2) + c * 256 + seg * 16;
            const char* pw = (const char*)W + (size_t)(nBase + row) * (KT * 2) + c * 256 + seg * 16;
            uint32_t off = SWZ256((uint32_t)row * 256 + seg * 16);
            *(uint4*)(smem + off)         = *(const uint4*)pa;
            *(uint4*)(smem + 32768 + off) = *(const uint4*)pw;
        }
        __syncthreads();

        #pragma unroll
        for (int kk = 0; kk < 8; kk++) {
            uint32_t a[4][4];
            #pragma unroll
            for (int mi = 0; mi < 4; mi++) {
                uint32_t byte = (uint32_t)(a_row_l + mi * 16) * 256 + (kk * 2 + a_chunk_l) * 16;
                uint32_t addr = sA + SWZ256(byte);
                asm volatile("ldmatrix.sync.aligned.m8n8.x4.shared.b16 {%0,%1,%2,%3}, [%4];"
                             : "=r"(a[mi][0]), "=r"(a[mi][1]), "=r"(a[mi][2]), "=r"(a[mi][3])
                             : "r"(addr));
            }
            uint32_t b[4][2];
            #pragma unroll
            for (int np = 0; np < 2; np++) {
                uint32_t byte = (uint32_t)(b_row_l + np * 16) * 256 + (kk * 2 + b_chunk_l) * 16;
                uint32_t addr = sB + SWZ256(byte);
                asm volatile("ldmatrix.sync.aligned.m8n8.x4.shared.b16 {%0,%1,%2,%3}, [%4];"
                             : "=r"(b[np*2][0]), "=r"(b[np*2][1]), "=r"(b[np*2+1][0]), "=r"(b[np*2+1][1])
                             : "r"(addr));
            }
            #pragma unroll
            for (int mi = 0; mi < 4; mi++)
                #pragma unroll
                for (int ni = 0; ni < 4; ni++)
                    asm volatile(
                        "mma.sync.aligned.m16n8k16.row.col.f32.bf16.bf16.f32 "
                        "{%0,%1,%2,%3}, {%4,%5,%6,%7}, {%8,%9}, {%0,%1,%2,%3};"
                        : "+f"(acc[mi][ni][0]), "+f"(acc[mi][ni][1]),
                          "+f"(acc[mi][ni][2]), "+f"(acc[mi][ni][3])
                        : "r"(a[mi][0]), "r"(a[mi][1]), "r"(a[mi][2]), "r"(a[mi][3]),
                          "r"(b[ni][0]), "r"(b[ni][1]));
        }
    }

    // Epilogue: bias + relu; MODE=0 writes split h, MODE=1 writes f32.
    int g0 = lane >> 2, q4 = lane & 3;
    #pragma unroll
    for (int mi = 0; mi < 4; mi++) {
        int row0 = mBase + warp_m * 64 + mi * 16 + g0;
        int row1 = row0 + 8;
        #pragma unroll
        for (int ni = 0; ni < 4; ni++) {
            int col = nBase + warp_n * 32 + ni * 8 + q4 * 2;
            float bv0 = bias[col], bv1 = bias[col + 1];
            float h00 = fmaxf(acc[mi][ni][0] + bv0, 0.0f);
            float h01 = fmaxf(acc[mi][ni][1] + bv1, 0.0f);
            float h10 = fmaxf(acc[mi][ni][2] + bv0, 0.0f);
            float h11 = fmaxf(acc[mi][ni][3] + bv1, 0.0f);
            if (MODE == 0) {
                __nv_bfloat16 a0 = __float2bfloat16_rn(h00), a1 = __float2bfloat16_rn(h01);
                __nv_bfloat16 c0 = __float2bfloat16_rn(h10), c1 = __float2bfloat16_rn(h11);
                __nv_bfloat162 hi0(a0, a1), hi1(c0, c1);
                __nv_bfloat162 lo0(__float2bfloat16_rn(h00 - __bfloat162float(a0)),
                                   __float2bfloat16_rn(h01 - __bfloat162float(a1)));
                __nv_bfloat162 lo1(__float2bfloat16_rn(h10 - __bfloat162float(c0)),
                                   __float2bfloat16_rn(h11 - __bfloat162float(c1)));
                __nv_bfloat162* p0 = (__nv_bfloat162*)(g_hpp + (size_t)row0 * KT + col);
                __nv_bfloat162* p1 = (__nv_bfloat162*)(g_hpp + (size_t)row1 * KT + col);
                p0[0] = hi0; p0[128] = hi0; p0[256] = lo0;   // cols +0 / +256 / +512
                p1[0] = hi1; p1[128] = hi1; p1[256] = lo1;
            } else {
                *(float2*)(g_h2 + (size_t)row0 * H2D + col) = make_float2(h00, h01);
                *(float2*)(g_h2 + (size_t)row1 * H2D + col) = make_float2(h10, h11);
            }
        }
    }
}

// ---------------------------------------------------------------------------
// Final layer: dot(h2[row], W3) + b3. One warp per row.
// ---------------------------------------------------------------------------
__global__ void layer3_kernel(const float* __restrict__ W3,
                              const float* __restrict__ b3,
                              float* __restrict__ out) {
    int warp = threadIdx.x >> 5;
    int lane = threadIdx.x & 31;
    int row  = blockIdx.x * 8 + warp;
    const float4* h = (const float4*)(g_h2 + (size_t)row * H2D);
    const float4* w = (const float4*)W3;
    float s = 0.0f;
    #pragma unroll
    for (int l = 0; l < 2; l++) {
        float4 hv = h[lane + 32 * l];
        float4 wv = w[lane + 32 * l];
        s += hv.x * wv.x + hv.y * wv.y + hv.z * wv.z + hv.w * wv.w;
    }
    #pragma unroll
    for (int o = 16; o > 0; o >>= 1) s += __shfl_xor_sync(0xffffffffu, s, o);
    if (lane == 0) out[row] = s + b3[0];
}

// ---------------------------------------------------------------------------
extern "C" void kernel_launch(void* const* d_in, const int* in_sizes, int n_in,
                              void* d_out, int out_size) {
    const float* x  = (const float*)d_in[0];
    const float* q  = (const float*)d_in[1];
    const float* W1 = (const float*)d_in[2];
    const float* b1 = (const float*)d_in[3];
    const float* W2 = (const float*)d_in[4];
    const float* b2 = (const float*)d_in[5];
    const float* W3 = (const float*)d_in[6];
    const float* b3 = (const float*)d_in[7];
    float* out = (float*)d_out;

    cudaFuncSetAttribute(gram_mma_kernel,
                         cudaFuncAttributeMaxDynamicSharedMemorySize, GRAM_SMEM_DYN);
    cudaFuncSetAttribute(mlp_mma_kernel<0>,
                         cudaFuncAttributeMaxDynamicSharedMemorySize, MLP_SMEM_DYN);
    cudaFuncSetAttribute(mlp_mma_kernel<1>,
                         cudaFuncAttributeMaxDynamicSharedMemorySize, MLP_SMEM_DYN);

    rownorm_kernel<<<B_ROWS / 8, 256>>>(x);
    prep_w_kernel<<<256, 256>>>(W1, W2);
    gram_mma_kernel<<<dim3(B_ROWS / 128, B_ROWS / 128), 256, GRAM_SMEM_DYN>>>();
    prep_feats_kernel<<<B_ROWS, 256>>>(x, q);
    mlp_mma_kernel<0><<<dim3(H1D / 128, B_ROWS / 128), 256, MLP_SMEM_DYN>>>(b1);
    mlp_mma_kernel<1><<<dim3(H2D / 128, B_ROWS / 128), 256, MLP_SMEM_DYN>>>(b2);
    layer3_kernel<<<B_ROWS / 8, 256>>>(W3, b3, out);
}

// round 10
// speedup vs baseline: 1.0026x; 1.0026x over previous
#include <cuda_runtime.h>
#include <cuda_bf16.h>
#include <cstdint>

#define B_ROWS 8192
#define F_DIM 128
#define Q_DIM 64
#define IN_DIM 193
#define H1D 256
#define H2D 256
#define THRESH 0.95f
#define EPSV 1e-12f

#define KT 768   // 3 segments of 256 cols

// Scratch (no allocations allowed)
__device__ __align__(16) __nv_bfloat16 g_xnb[B_ROWS * F_DIM];
__device__ int   g_cnt[B_ROWS];
__device__ __align__(16) __nv_bfloat16 g_fpp[B_ROWS * KT];   // [fh|fh|fl]
__device__ __align__(16) __nv_bfloat16 g_w1pp[H1D * KT];     // [wh|wl|wh]
__device__ __align__(16) __nv_bfloat16 g_hpp[B_ROWS * KT];   // [hh|hh|hl]
__device__ __align__(16) __nv_bfloat16 g_w2pp[H2D * KT];     // [wh|wl|wh]
__device__ __align__(16) float g_h2[B_ROWS * H2D];

__device__ __forceinline__ uint32_t smem_u32(const void* p) {
    uint32_t a;
    asm("{ .reg .u64 t; cvta.to.shared.u64 t, %1; cvt.u32.u64 %0, t; }" : "=r"(a) : "l"(p));
    return a;
}
#define SWZ256(b) ((b) ^ ((((b) >> 8) & 7) << 4))

// ---------------------------------------------------------------------------
// Kernel 1: row L2 norm -> bf16 normalized rows; zero counters
// ---------------------------------------------------------------------------
__global__ void rownorm_kernel(const float* __restrict__ x) {
    int row  = blockIdx.x * 8 + (threadIdx.x >> 5);
    int lane = threadIdx.x & 31;
    const float4* xr = (const float4*)(x + (size_t)row * F_DIM);
    float4 v = xr[lane];
    float s = v.x * v.x + v.y * v.y + v.z * v.z + v.w * v.w;
    #pragma unroll
    for (int o = 16; o > 0; o >>= 1) s += __shfl_xor_sync(0xffffffffu, s, o);
    float inv = 1.0f / (sqrtf(s) + EPSV);
    __nv_bfloat162* outp = (__nv_bfloat162*)(g_xnb + (size_t)row * F_DIM);
    outp[lane * 2 + 0] = __nv_bfloat162(__float2bfloat16_rn(v.x * inv), __float2bfloat16_rn(v.y * inv));
    outp[lane * 2 + 1] = __nv_bfloat162(__float2bfloat16_rn(v.z * inv), __float2bfloat16_rn(v.w * inv));
    if (lane == 0) g_cnt[row] = 0;
}

// ---------------------------------------------------------------------------
// Kernel 2: symmetric gram-count (HMMA). Upper-triangle tiles only. (proven)
// ---------------------------------------------------------------------------
#define GRAM_SMEM_DYN 65536

__global__ void __launch_bounds__(256) gram_mma_kernel() {
    int bi = blockIdx.y, bj = blockIdx.x;
    if (bj < bi) return;
    const bool diag = (bi == bj);

    extern __shared__ char smem[];
    int t = threadIdx.x, wid = t >> 5, lane = t & 31;
    int warp_m = wid >> 2, warp_n = wid & 3;
    int rowBase = bi * 128;
    int colBase = bj * 128;

    uint32_t sA = smem_u32(smem);
    uint32_t sB = sA + 32768;

    #pragma unroll
    for (int l = 0; l < 8; l++) {
        int u = t + l * 256;
        int row = u >> 4, seg = u & 15;
        uint4 va = ((const uint4*)(g_xnb + (size_t)(rowBase + row) * F_DIM))[seg];
        uint4 vb = ((const uint4*)(g_xnb + (size_t)(colBase + row) * F_DIM))[seg];
        uint32_t off = SWZ256((uint32_t)row * 256 + seg * 16);
        *(uint4*)(smem + off)         = va;
        *(uint4*)(smem + 32768 + off) = vb;
    }
    __syncthreads();

    int a_row_l   = warp_m * 64 + (lane & 15);
    int a_chunk_l = lane >> 4;
    int b_row_l   = warp_n * 32 + ((lane >> 4) << 3) + (lane & 7);
    int b_chunk_l = (lane >> 3) & 1;

    float acc[4][4][4];
    #pragma unroll
    for (int mi = 0; mi < 4; mi++)
        #pragma unroll
        for (int ni = 0; ni < 4; ni++)
            #pragma unroll
            for (int r = 0; r < 4; r++) acc[mi][ni][r] = 0.0f;

    #pragma unroll
    for (int kk = 0; kk < 8; kk++) {
        uint32_t a[4][4];
        #pragma unroll
        for (int mi = 0; mi < 4; mi++) {
            uint32_t byte = (uint32_t)(a_row_l + mi * 16) * 256 + (kk * 2 + a_chunk_l) * 16;
            uint32_t addr = sA + SWZ256(byte);
            asm volatile("ldmatrix.sync.aligned.m8n8.x4.shared.b16 {%0,%1,%2,%3}, [%4];"
                         : "=r"(a[mi][0]), "=r"(a[mi][1]), "=r"(a[mi][2]), "=r"(a[mi][3])
                         : "r"(addr));
        }
        uint32_t b[4][2];
        #pragma unroll
        for (int np = 0; np < 2; np++) {
            uint32_t byte = (uint32_t)(b_row_l + np * 16) * 256 + (kk * 2 + b_chunk_l) * 16;
            uint32_t addr = sB + SWZ256(byte);
            asm volatile("ldmatrix.sync.aligned.m8n8.x4.shared.b16 {%0,%1,%2,%3}, [%4];"
                         : "=r"(b[np*2][0]), "=r"(b[np*2][1]), "=r"(b[np*2+1][0]), "=r"(b[np*2+1][1])
                         : "r"(addr));
        }
        #pragma unroll
        for (int mi = 0; mi < 4; mi++)
            #pragma unroll
            for (int ni = 0; ni < 4; ni++)
                asm volatile(
                    "mma.sync.aligned.m16n8k16.row.col.f32.bf16.bf16.f32 "
                    "{%0,%1,%2,%3}, {%4,%5,%6,%7}, {%8,%9}, {%0,%1,%2,%3};"
                    : "+f"(acc[mi][ni][0]), "+f"(acc[mi][ni][1]),
                      "+f"(acc[mi][ni][2]), "+f"(acc[mi][ni][3])
                    : "r"(a[mi][0]), "r"(a[mi][1]), "r"(a[mi][2]), "r"(a[mi][3]),
                      "r"(b[ni][0]), "r"(b[ni][1]));
    }

    int g0 = lane >> 2, q4 = lane & 3;
    #pragma unroll
    for (int mi = 0; mi < 4; mi++) {
        int row0 = rowBase + warp_m * 64 + mi * 16 + g0;
        int row1 = row0 + 8;
        #pragma unroll
        for (int ni = 0; ni < 4; ni++) {
            int c0 = colBase + warp_n * 32 + ni * 8 + q4 * 2;
            #pragma unroll
            for (int r = 0; r < 4; r++) {
                int row = (r < 2) ? row0 : row1;
                int col = c0 + (r & 1);
                float v = acc[mi][ni][r];
                if (v * v >= THRESH && row != col) {
                    atomicAdd(&g_cnt[row], 1);
                    if (!diag) atomicAdd(&g_cnt[col], 1);
                }
            }
        }
    }
}

// ---------------------------------------------------------------------------
// Prep: split-bf16 buffers (all writes to device globals, referenced directly).
// A-side segments [hi|hi|lo]; W-side segments [hi|lo|hi].
// ---------------------------------------------------------------------------
__global__ void prep_feats_kernel(const float* __restrict__ x,
                                  const float* __restrict__ q) {
    int row = blockIdx.x;
    int k = threadIdx.x;                         // 0..255
    float f = 0.0f;
    if (k < F_DIM)               f = x[(size_t)row * F_DIM + k];
    else if (k < F_DIM + Q_DIM)  f = q[(size_t)row * Q_DIM + (k - F_DIM)];
    else if (k == IN_DIM - 1)    f = (float)g_cnt[row] * (1.0f / (float)B_ROWS);
    __nv_bfloat16 hi = __float2bfloat16_rn(f);
    __nv_bfloat16 lo = __float2bfloat16_rn(f - __bfloat162float(hi));
    size_t base = (size_t)row * KT;
    g_fpp[base + k]       = hi;
    g_fpp[base + 256 + k] = hi;
    g_fpp[base + 512 + k] = lo;
}

__global__ void prep_w_kernel(const float* __restrict__ W1,
                              const float* __restrict__ W2) {
    int n = blockIdx.x;                          // 0..255
    int k = threadIdx.x;                         // 0..255
    {
        float f = (k < IN_DIM) ? W1[(size_t)n * IN_DIM + k] : 0.0f;
        __nv_bfloat16 hi = __float2bfloat16_rn(f);
        __nv_bfloat16 lo = __float2bfloat16_rn(f - __bfloat162float(hi));
        size_t base = (size_t)n * KT;
        g_w1pp[base + k]       = hi;
        g_w1pp[base + 256 + k] = lo;
        g_w1pp[base + 512 + k] = hi;
    }
    {
        float f = W2[(size_t)n * H1D + k];
        __nv_bfloat16 hi = __float2bfloat16_rn(f);
        __nv_bfloat16 lo = __float2bfloat16_rn(f - __bfloat162float(hi));
        size_t base = (size_t)n * KT;
        g_w2pp[base + k]       = hi;
        g_w2pp[base + 256 + k] = lo;
        g_w2pp[base + 512 + k] = hi;
    }
}

// ---------------------------------------------------------------------------
// MLP GEMM (HMMA): K=768 in 6 chunks of 128 cols. A/W are device globals
// selected by MODE *inside device code* (NOT passed as host-side args — that
// was the R5/R7 bug: host address of __device__ symbols).
// MODE 0: A=g_fpp, W=g_w1pp, +b1, relu, split -> g_hpp.
// MODE 1: A=g_hpp, W=g_w2pp, +b2, relu -> g_h2 (f32).
// ---------------------------------------------------------------------------
#define MLP_SMEM_DYN 65536

template <int MODE>
__global__ void __launch_bounds__(256) mlp_mma_kernel(const float* __restrict__ bias) {
    const __nv_bfloat16* A = (MODE == 0) ? g_fpp  : g_hpp;
    const __nv_bfloat16* W = (MODE == 0) ? g_w1pp : g_w2pp;

    extern __shared__ char smem[];
    int t = threadIdx.x, wid = t >> 5, lane = t & 31;
    int warp_m = wid >> 2, warp_n = wid & 3;
    int mBase = blockIdx.y * 128;
    int nBase = blockIdx.x * 128;

    uint32_t sA = smem_u32(smem);
    uint32_t sB = sA + 32768;

    int a_row_l   = warp_m * 64 + (lane & 15);
    int a_chunk_l = lane >> 4;
    int b_row_l   = warp_n * 32 + ((lane >> 4) << 3) + (lane & 7);
    int b_chunk_l = (lane >> 3) & 1;

    float acc[4][4][4];
    #pragma unroll
    for (int mi = 0; mi < 4; mi++)
        #pragma unroll
        for (int ni = 0; ni < 4; ni++)
            #pragma unroll
            for (int r = 0; r < 4; r++) acc[mi][ni][r] = 0.0f;

    for (int c = 0; c < KT / 128; c++) {
        if (c) __syncthreads();                  // previous chunk fully consumed
        #pragma unroll
        for (int l = 0; l < 8; l++) {
            int u = t + l * 256;
            int row = u >> 4, seg = u & 15;
            // rows are KT bf16 = 1536B; take this chunk's 256B slice
            const char* pa = (const char*)A + (size_t)(mBase + row) * (KT * 2) + c * 256 + seg * 16;
            const char* pw = (const char*)W + (size_t)(nBase + row) * (KT * 2) + c * 256 + seg * 16;
            uint32_t off = SWZ256((uint32_t)row * 256 + seg * 16);
            *(uint4*)(smem + off)         = *(const uint4*)pa;
            *(uint4*)(smem + 32768 + off) = *(const uint4*)pw;
        }
        __syncthreads();

        #pragma unroll
        for (int kk = 0; kk < 8; kk++) {
            uint32_t a[4][4];
            #pragma unroll
            for (int mi = 0; mi < 4; mi++) {
                uint32_t byte = (uint32_t)(a_row_l + mi * 16) * 256 + (kk * 2 + a_chunk_l) * 16;
                uint32_t addr = sA + SWZ256(byte);
                asm volatile("ldmatrix.sync.aligned.m8n8.x4.shared.b16 {%0,%1,%2,%3}, [%4];"
                             : "=r"(a[mi][0]), "=r"(a[mi][1]), "=r"(a[mi][2]), "=r"(a[mi][3])
                             : "r"(addr));
            }
            uint32_t b[4][2];
            #pragma unroll
            for (int np = 0; np < 2; np++) {
                uint32_t byte = (uint32_t)(b_row_l + np * 16) * 256 + (kk * 2 + b_chunk_l) * 16;
                uint32_t addr = sB + SWZ256(byte);
                asm volatile("ldmatrix.sync.aligned.m8n8.x4.shared.b16 {%0,%1,%2,%3}, [%4];"
                             : "=r"(b[np*2][0]), "=r"(b[np*2][1]), "=r"(b[np*2+1][0]), "=r"(b[np*2+1][1])
                             : "r"(addr));
            }
            #pragma unroll
            for (int mi = 0; mi < 4; mi++)
                #pragma unroll
                for (int ni = 0; ni < 4; ni++)
                    asm volatile(
                        "mma.sync.aligned.m16n8k16.row.col.f32.bf16.bf16.f32 "
                        "{%0,%1,%2,%3}, {%4,%5,%6,%7}, {%8,%9}, {%0,%1,%2,%3};"
                        : "+f"(acc[mi][ni][0]), "+f"(acc[mi][ni][1]),
                          "+f"(acc[mi][ni][2]), "+f"(acc[mi][ni][3])
                        : "r"(a[mi][0]), "r"(a[mi][1]), "r"(a[mi][2]), "r"(a[mi][3]),
                          "r"(b[ni][0]), "r"(b[ni][1]));
        }
    }

    // Epilogue: bias + relu; MODE=0 writes split h, MODE=1 writes f32.
    int g0 = lane >> 2, q4 = lane & 3;
    #pragma unroll
    for (int mi = 0; mi < 4; mi++) {
        int row0 = mBase + warp_m * 64 + mi * 16 + g0;
        int row1 = row0 + 8;
        #pragma unroll
        for (int ni = 0; ni < 4; ni++) {
            int col = nBase + warp_n * 32 + ni * 8 + q4 * 2;
            float bv0 = bias[col], bv1 = bias[col + 1];
            float h00 = fmaxf(acc[mi][ni][0] + bv0, 0.0f);
            float h01 = fmaxf(acc[mi][ni][1] + bv1, 0.0f);
            float h10 = fmaxf(acc[mi][ni][2] + bv0, 0.0f);
            float h11 = fmaxf(acc[mi][ni][3] + bv1, 0.0f);
            if (MODE == 0) {
                __nv_bfloat16 a0 = __float2bfloat16_rn(h00), a1 = __float2bfloat16_rn(h01);
                __nv_bfloat16 c0 = __float2bfloat16_rn(h10), c1 = __float2bfloat16_rn(h11);
                __nv_bfloat162 hi0(a0, a1), hi1(c0, c1);
                __nv_bfloat162 lo0(__float2bfloat16_rn(h00 - __bfloat162float(a0)),
                                   __float2bfloat16_rn(h01 - __bfloat162float(a1)));
                __nv_bfloat162 lo1(__float2bfloat16_rn(h10 - __bfloat162float(c0)),
                                   __float2bfloat16_rn(h11 - __bfloat162float(c1)));
                __nv_bfloat162* p0 = (__nv_bfloat162*)(g_hpp + (size_t)row0 * KT + col);
                __nv_bfloat162* p1 = (__nv_bfloat162*)(g_hpp + (size_t)row1 * KT + col);
                p0[0] = hi0; p0[128] = hi0; p0[256] = lo0;   // cols +0 / +256 / +512
                p1[0] = hi1; p1[128] = hi1; p1[256] = lo1;
            } else {
                *(float2*)(g_h2 + (size_t)row0 * H2D + col) = make_float2(h00, h01);
                *(float2*)(g_h2 + (size_t)row1 * H2D + col) = make_float2(h10, h11);
            }
        }
    }
}

// ---------------------------------------------------------------------------
// Final layer: dot(h2[row], W3) + b3. One warp per row.
// ---------------------------------------------------------------------------
__global__ void layer3_kernel(const float* __restrict__ W3,
                              const float* __restrict__ b3,
                              float* __restrict__ out) {
    int warp = threadIdx.x >> 5;
    int lane = threadIdx.x & 31;
    int row  = blockIdx.x * 8 + warp;
    const float4* h = (const float4*)(g_h2 + (size_t)row * H2D);
    const float4* w = (const float4*)W3;
    float s = 0.0f;
    #pragma unroll
    for (int l = 0; l < 2; l++) {
        float4 hv = h[lane + 32 * l];
        float4 wv = w[lane + 32 * l];
        s += hv.x * wv.x + hv.y * wv.y + hv.z * wv.z + hv.w * wv.w;
    }
    #pragma unroll
    for (int o = 16; o > 0; o >>= 1) s += __shfl_xor_sync(0xffffffffu, s, o);
    if (lane == 0) out[row] = s + b3[0];
}

// ---------------------------------------------------------------------------
extern "C" void kernel_launch(void* const* d_in, const int* in_sizes, int n_in,
                              void* d_out, int out_size) {
    const float* x  = (const float*)d_in[0];
    const float* q  = (const float*)d_in[1];
    const float* W1 = (const float*)d_in[2];
    const float* b1 = (const float*)d_in[3];
    const float* W2 = (const float*)d_in[4];
    const float* b2 = (const float*)d_in[5];
    const float* W3 = (const float*)d_in[6];
    const float* b3 = (const float*)d_in[7];
    float* out = (float*)d_out;

    cudaFuncSetAttribute(gram_mma_kernel,
                         cudaFuncAttributeMaxDynamicSharedMemorySize, GRAM_SMEM_DYN);
    cudaFuncSetAttribute(mlp_mma_kernel<0>,
                         cudaFuncAttributeMaxDynamicSharedMemorySize, MLP_SMEM_DYN);
    cudaFuncSetAttribute(mlp_mma_kernel<1>,
                         cudaFuncAttributeMaxDynamicSharedMemorySize, MLP_SMEM_DYN);

    rownorm_kernel<<<B_ROWS / 8, 256>>>(x);
    prep_w_kernel<<<256, 256>>>(W1, W2);
    gram_mma_kernel<<<dim3(B_ROWS / 128, B_ROWS / 128), 256, GRAM_SMEM_DYN>>>();
    prep_feats_kernel<<<B_ROWS, 256>>>(x, q);
    mlp_mma_kernel<0><<<dim3(H1D / 128, B_ROWS / 128), 256, MLP_SMEM_DYN>>>(b1);
    mlp_mma_kernel<1><<<dim3(H2D / 128, B_ROWS / 128), 256, MLP_SMEM_DYN>>>(b2);
    layer3_kernel<<<B_ROWS / 8, 256>>>(W3, b3, out);
}

// round 11
// speedup vs baseline: 1.0082x; 1.0056x over previous
#include <cuda_runtime.h>
#include <cuda_bf16.h>
#include <cstdint>

#define B_ROWS 8192
#define F_DIM 128
#define Q_DIM 64
#define IN_DIM 193
#define H1D 256
#define H2D 256
#define THRESH 0.95f
#define EPSV 1e-12f

#define KT 768   // 3 segments of 256 cols

// Scratch (no allocations allowed)
__device__ __align__(16) __nv_bfloat16 g_xnb[B_ROWS * F_DIM];
__device__ int   g_cnt[B_ROWS];
__device__ __align__(16) __nv_bfloat16 g_fpp[B_ROWS * KT];   // [fh|fh|fl]
__device__ __align__(16) __nv_bfloat16 g_w1pp[H1D * KT];     // [wh|wl|wh]
__device__ __align__(16) __nv_bfloat16 g_hpp[B_ROWS * KT];   // [hh|hh|hl]
__device__ __align__(16) __nv_bfloat16 g_w2pp[H2D * KT];     // [wh|wl|wh]
__device__ __align__(16) float g_h2[B_ROWS * H2D];

__device__ __forceinline__ uint32_t smem_u32(const void* p) {
    uint32_t a;
    asm("{ .reg .u64 t; cvta.to.shared.u64 t, %1; cvt.u32.u64 %0, t; }" : "=r"(a) : "l"(p));
    return a;
}
#define SWZ256(b) ((b) ^ ((((b) >> 8) & 7) << 4))

// ---------------------------------------------------------------------------
// Kernel 1: row L2 norm -> bf16 normalized rows; zero counters
// ---------------------------------------------------------------------------
__global__ void rownorm_kernel(const float* __restrict__ x) {
    int row  = blockIdx.x * 8 + (threadIdx.x >> 5);
    int lane = threadIdx.x & 31;
    const float4* xr = (const float4*)(x + (size_t)row * F_DIM);
    float4 v = xr[lane];
    float s = v.x * v.x + v.y * v.y + v.z * v.z + v.w * v.w;
    #pragma unroll
    for (int o = 16; o > 0; o >>= 1) s += __shfl_xor_sync(0xffffffffu, s, o);
    float inv = 1.0f / (sqrtf(s) + EPSV);
    __nv_bfloat162* outp = (__nv_bfloat162*)(g_xnb + (size_t)row * F_DIM);
    outp[lane * 2 + 0] = __nv_bfloat162(__float2bfloat16_rn(v.x * inv), __float2bfloat16_rn(v.y * inv));
    outp[lane * 2 + 1] = __nv_bfloat162(__float2bfloat16_rn(v.z * inv), __float2bfloat16_rn(v.w * inv));
    if (lane == 0) g_cnt[row] = 0;
}

// ---------------------------------------------------------------------------
// Kernel 2: symmetric gram-count (HMMA). Upper-triangle tiles only. (proven)
// ---------------------------------------------------------------------------
#define GRAM_SMEM_DYN 65536

__global__ void __launch_bounds__(256) gram_mma_kernel() {
    int bi = blockIdx.y, bj = blockIdx.x;
    if (bj < bi) return;
    const bool diag = (bi == bj);

    extern __shared__ char smem[];
    int t = threadIdx.x, wid = t >> 5, lane = t & 31;
    int warp_m = wid >> 2, warp_n = wid & 3;
    int rowBase = bi * 128;
    int colBase = bj * 128;

    uint32_t sA = smem_u32(smem);
    uint32_t sB = sA + 32768;

    #pragma unroll
    for (int l = 0; l < 8; l++) {
        int u = t + l * 256;
        int row = u >> 4, seg = u & 15;
        uint4 va = ((const uint4*)(g_xnb + (size_t)(rowBase + row) * F_DIM))[seg];
        uint4 vb = ((const uint4*)(g_xnb + (size_t)(colBase + row) * F_DIM))[seg];
        uint32_t off = SWZ256((uint32_t)row * 256 + seg * 16);
        *(uint4*)(smem + off)         = va;
        *(uint4*)(smem + 32768 + off) = vb;
    }
    __syncthreads();

    int a_row_l   = warp_m * 64 + (lane & 15);
    int a_chunk_l = lane >> 4;
    int b_row_l   = warp_n * 32 + ((lane >> 4) << 3) + (lane & 7);
    int b_chunk_l = (lane >> 3) & 1;

    float acc[4][4][4];
    #pragma unroll
    for (int mi = 0; mi < 4; mi++)
        #pragma unroll
        for (int ni = 0; ni < 4; ni++)
            #pragma unroll
            for (int r = 0; r < 4; r++) acc[mi][ni][r] = 0.0f;

    #pragma unroll
    for (int kk = 0; kk < 8; kk++) {
        uint32_t a[4][4];
        #pragma unroll
        for (int mi = 0; mi < 4; mi++) {
            uint32_t byte = (uint32_t)(a_row_l + mi * 16) * 256 + (kk * 2 + a_chunk_l) * 16;
            uint32_t addr = sA + SWZ256(byte);
            asm volatile("ldmatrix.sync.aligned.m8n8.x4.shared.b16 {%0,%1,%2,%3}, [%4];"
                         : "=r"(a[mi][0]), "=r"(a[mi][1]), "=r"(a[mi][2]), "=r"(a[mi][3])
                         : "r"(addr));
        }
        uint32_t b[4][2];
        #pragma unroll
        for (int np = 0; np < 2; np++) {
            uint32_t byte = (uint32_t)(b_row_l + np * 16) * 256 + (kk * 2 + b_chunk_l) * 16;
            uint32_t addr = sB + SWZ256(byte);
            asm volatile("ldmatrix.sync.aligned.m8n8.x4.shared.b16 {%0,%1,%2,%3}, [%4];"
                         : "=r"(b[np*2][0]), "=r"(b[np*2][1]), "=r"(b[np*2+1][0]), "=r"(b[np*2+1][1])
                         : "r"(addr));
        }
        #pragma unroll
        for (int mi = 0; mi < 4; mi++)
            #pragma unroll
            for (int ni = 0; ni < 4; ni++)
                asm volatile(
                    "mma.sync.aligned.m16n8k16.row.col.f32.bf16.bf16.f32 "
                    "{%0,%1,%2,%3}, {%4,%5,%6,%7}, {%8,%9}, {%0,%1,%2,%3};"
                    : "+f"(acc[mi][ni][0]), "+f"(acc[mi][ni][1]),
                      "+f"(acc[mi][ni][2]), "+f"(acc[mi][ni][3])
                    : "r"(a[mi][0]), "r"(a[mi][1]), "r"(a[mi][2]), "r"(a[mi][3]),
                      "r"(b[ni][0]), "r"(b[ni][1]));
    }

    int g0 = lane >> 2, q4 = lane & 3;
    #pragma unroll
    for (int mi = 0; mi < 4; mi++) {
        int row0 = rowBase + warp_m * 64 + mi * 16 + g0;
        int row1 = row0 + 8;
        #pragma unroll
        for (int ni = 0; ni < 4; ni++) {
            int c0 = colBase + warp_n * 32 + ni * 8 + q4 * 2;
            #pragma unroll
            for (int r = 0; r < 4; r++) {
                int row = (r < 2) ? row0 : row1;
                int col = c0 + (r & 1);
                float v = acc[mi][ni][r];
                if (v * v >= THRESH && row != col) {
                    atomicAdd(&g_cnt[row], 1);
                    if (!diag) atomicAdd(&g_cnt[col], 1);
                }
            }
        }
    }
}

// ---------------------------------------------------------------------------
// Prep: split-bf16 buffers (all writes to device globals, referenced directly).
// A-side segments [hi|hi|lo]; W-side segments [hi|lo|hi].
// ---------------------------------------------------------------------------
__global__ void prep_feats_kernel(const float* __restrict__ x,
                                  const float* __restrict__ q) {
    int row = blockIdx.x;
    int k = threadIdx.x;                         // 0..255
    float f = 0.0f;
    if (k < F_DIM)               f = x[(size_t)row * F_DIM + k];
    else if (k < F_DIM + Q_DIM)  f = q[(size_t)row * Q_DIM + (k - F_DIM)];
    else if (k == IN_DIM - 1)    f = (float)g_cnt[row] * (1.0f / (float)B_ROWS);
    __nv_bfloat16 hi = __float2bfloat16_rn(f);
    __nv_bfloat16 lo = __float2bfloat16_rn(f - __bfloat162float(hi));
    size_t base = (size_t)row * KT;
    g_fpp[base + k]       = hi;
    g_fpp[base + 256 + k] = hi;
    g_fpp[base + 512 + k] = lo;
}

__global__ void prep_w_kernel(const float* __restrict__ W1,
                              const float* __restrict__ W2) {
    int n = blockIdx.x;                          // 0..255
    int k = threadIdx.x;                         // 0..255
    {
        float f = (k < IN_DIM) ? W1[(size_t)n * IN_DIM + k] : 0.0f;
        __nv_bfloat16 hi = __float2bfloat16_rn(f);
        __nv_bfloat16 lo = __float2bfloat16_rn(f - __bfloat162float(hi));
        size_t base = (size_t)n * KT;
        g_w1pp[base + k]       = hi;
        g_w1pp[base + 256 + k] = lo;
        g_w1pp[base + 512 + k] = hi;
    }
    {
        float f = W2[(size_t)n * H1D + k];
        __nv_bfloat16 hi = __float2bfloat16_rn(f);
        __nv_bfloat16 lo = __float2bfloat16_rn(f - __bfloat162float(hi));
        size_t base = (size_t)n * KT;
        g_w2pp[base + k]       = hi;
        g_w2pp[base + 256 + k] = lo;
        g_w2pp[base + 512 + k] = hi;
    }
}

// ---------------------------------------------------------------------------
// MLP GEMM (HMMA): K=768 in 6 chunks of 128 cols. A/W are device globals
// selected by MODE *inside device code* (NOT passed as host-side args — that
// was the R5/R7 bug: host address of __device__ symbols).
// MODE 0: A=g_fpp, W=g_w1pp, +b1, relu, split -> g_hpp.
// MODE 1: A=g_hpp, W=g_w2pp, +b2, relu -> g_h2 (f32).
// ---------------------------------------------------------------------------
#define MLP_SMEM_DYN 65536

template <int MODE>
__global__ void __launch_bounds__(256) mlp_mma_kernel(const float* __restrict__ bias) {
    const __nv_bfloat16* A = (MODE == 0) ? g_fpp  : g_hpp;
    const __nv_bfloat16* W = (MODE == 0) ? g_w1pp : g_w2pp;

    extern __shared__ char smem[];
    int t = threadIdx.x, wid = t >> 5, lane = t & 31;
    int warp_m = wid >> 2, warp_n = wid & 3;
    int mBase = blockIdx.y * 128;
    int nBase = blockIdx.x * 128;

    uint32_t sA = smem_u32(smem);
    uint32_t sB = sA + 32768;

    int a_row_l   = warp_m * 64 + (lane & 15);
    int a_chunk_l = lane >> 4;
    int b_row_l   = warp_n * 32 + ((lane >> 4) << 3) + (lane & 7);
    int b_chunk_l = (lane >> 3) & 1;

    float acc[4][4][4];
    #pragma unroll
    for (int mi = 0; mi < 4; mi++)
        #pragma unroll
        for (int ni = 0; ni < 4; ni++)
            #pragma unroll
            for (int r = 0; r < 4; r++) acc[mi][ni][r] = 0.0f;

    for (int c = 0; c < KT / 128; c++) {
        if (c) __syncthreads();                  // previous chunk fully consumed
        #pragma unroll
        for (int l = 0; l < 8; l++) {
            int u = t + l * 256;
            int row = u >> 4, seg = u & 15;
            // rows are KT bf16 = 1536B; take this chunk's 256B slice
            const char* pa = (const char*)A + (size_t)(mBase + row) * (KT * 2) + c * 256 + seg * 16;
            const char* pw = (const char*)W + (size_t)(nBase + row) * (KT * 2) + c * 256 + seg * 16;
            uint32_t off = SWZ256((uint32_t)row * 256 + seg * 16);
            *(uint4*)(smem + off)         = *(const uint4*)pa;
            *(uint4*)(smem + 32768 + off) = *(const uint4*)pw;
        }
        __syncthreads();

        #pragma unroll
        for (int kk = 0; kk < 8; kk++) {
            uint32_t a[4][4];
            #pragma unroll
            for (int mi = 0; mi < 4; mi++) {
                uint32_t byte = (uint32_t)(a_row_l + mi * 16) * 256 + (kk * 2 + a_chunk_l) * 16;
                uint32_t addr = sA + SWZ256(byte);
                asm volatile("ldmatrix.sync.aligned.m8n8.x4.shared.b16 {%0,%1,%2,%3}, [%4];"
                             : "=r"(a[mi][0]), "=r"(a[mi][1]), "=r"(a[mi][2]), "=r"(a[mi][3])
                             : "r"(addr));
            }
            uint32_t b[4][2];
            #pragma unroll
            for (int np = 0; np < 2; np++) {
                uint32_t byte = (uint32_t)(b_row_l + np * 16) * 256 + (kk * 2 + b_chunk_l) * 16;
                uint32_t addr = sB + SWZ256(byte);
                asm volatile("ldmatrix.sync.aligned.m8n8.x4.shared.b16 {%0,%1,%2,%3}, [%4];"
                             : "=r"(b[np*2][0]), "=r"(b[np*2][1]), "=r"(b[np*2+1][0]), "=r"(b[np*2+1][1])
                             : "r"(addr));
            }
            #pragma unroll
            for (int mi = 0; mi < 4; mi++)
                #pragma unroll
                for (int ni = 0; ni < 4; ni++)
                    asm volatile(
                        "mma.sync.aligned.m16n8k16.row.col.f32.bf16.bf16.f32 "
                        "{%0,%1,%2,%3}, {%4,%5,%6,%7}, {%8,%9}, {%0,%1,%2,%3};"
                        : "+f"(acc[mi][ni][0]), "+f"(acc[mi][ni][1]),
                          "+f"(acc[mi][ni][2]), "+f"(acc[mi][ni][3])
                        : "r"(a[mi][0]), "r"(a[mi][1]), "r"(a[mi][2]), "r"(a[mi][3]),
                          "r"(b[ni][0]), "r"(b[ni][1]));
        }
    }

    // Epilogue: bias + relu; MODE=0 writes split h, MODE=1 writes f32.
    int g0 = lane >> 2, q4 = lane & 3;
    #pragma unroll
    for (int mi = 0; mi < 4; mi++) {
        int row0 = mBase + warp_m * 64 + mi * 16 + g0;
        int row1 = row0 + 8;
        #pragma unroll
        for (int ni = 0; ni < 4; ni++) {
            int col = nBase + warp_n * 32 + ni * 8 + q4 * 2;
            float bv0 = bias[col], bv1 = bias[col + 1];
            float h00 = fmaxf(acc[mi][ni][0] + bv0, 0.0f);
            float h01 = fmaxf(acc[mi][ni][1] + bv1, 0.0f);
            float h10 = fmaxf(acc[mi][ni][2] + bv0, 0.0f);
            float h11 = fmaxf(acc[mi][ni][3] + bv1, 0.0f);
            if (MODE == 0) {
                __nv_bfloat16 a0 = __float2bfloat16_rn(h00), a1 = __float2bfloat16_rn(h01);
                __nv_bfloat16 c0 = __float2bfloat16_rn(h10), c1 = __float2bfloat16_rn(h11);
                __nv_bfloat162 hi0(a0, a1), hi1(c0, c1);
                __nv_bfloat162 lo0(__float2bfloat16_rn(h00 - __bfloat162float(a0)),
                                   __float2bfloat16_rn(h01 - __bfloat162float(a1)));
                __nv_bfloat162 lo1(__float2bfloat16_rn(h10 - __bfloat162float(c0)),
                                   __float2bfloat16_rn(h11 - __bfloat162float(c1)));
                __nv_bfloat162* p0 = (__nv_bfloat162*)(g_hpp + (size_t)row0 * KT + col);
                __nv_bfloat162* p1 = (__nv_bfloat162*)(g_hpp + (size_t)row1 * KT + col);
                p0[0] = hi0; p0[128] = hi0; p0[256] = lo0;   // cols +0 / +256 / +512
                p1[0] = hi1; p1[128] = hi1; p1[256] = lo1;
            } else {
                *(float2*)(g_h2 + (size_t)row0 * H2D + col) = make_float2(h00, h01);
                *(float2*)(g_h2 + (size_t)row1 * H2D + col) = make_float2(h10, h11);
            }
        }
    }
}

// ---------------------------------------------------------------------------
// Final layer: dot(h2[row], W3) + b3. One warp per row.
// ---------------------------------------------------------------------------
__global__ void layer3_kernel(const float* __restrict__ W3,
                              const float* __restrict__ b3,
                              float* __restrict__ out) {
    int warp = threadIdx.x >> 5;
    int lane = threadIdx.x & 31;
    int row  = blockIdx.x * 8 + warp;
    const float4* h = (const float4*)(g_h2 + (size_t)row * H2D);
    const float4* w = (const float4*)W3;
    float s = 0.0f;
    #pragma unroll
    for (int l = 0; l < 2; l++) {
        float4 hv = h[lane + 32 * l];
        float4 wv = w[lane + 32 * l];
        s += hv.x * wv.x + hv.y * wv.y + hv.z * wv.z + hv.w * wv.w;
    }
    #pragma unroll
    for (int o = 16; o > 0; o >>= 1) s += __shfl_xor_sync(0xffffffffu, s, o);
    if (lane == 0) out[row] = s + b3[0];
}

// ---------------------------------------------------------------------------
extern "C" void kernel_launch(void* const* d_in, const int* in_sizes, int n_in,
                              void* d_out, int out_size) {
    const float* x  = (const float*)d_in[0];
    const float* q  = (const float*)d_in[1];
    const float* W1 = (const float*)d_in[2];
    const float* b1 = (const float*)d_in[3];
    const float* W2 = (const float*)d_in[4];
    const float* b2 = (const float*)d_in[5];
    const float* W3 = (const float*)d_in[6];
    const float* b3 = (const float*)d_in[7];
    float* out = (float*)d_out;

    cudaFuncSetAttribute(gram_mma_kernel,
                         cudaFuncAttributeMaxDynamicSharedMemorySize, GRAM_SMEM_DYN);
    cudaFuncSetAttribute(mlp_mma_kernel<0>,
                         cudaFuncAttributeMaxDynamicSharedMemorySize, MLP_SMEM_DYN);
    cudaFuncSetAttribute(mlp_mma_kernel<1>,
                         cudaFuncAttributeMaxDynamicSharedMemorySize, MLP_SMEM_DYN);

    rownorm_kernel<<<B_ROWS / 8, 256>>>(x);
    prep_w_kernel<<<256, 256>>>(W1, W2);
    gram_mma_kernel<<<dim3(B_ROWS / 128, B_ROWS / 128), 256, GRAM_SMEM_DYN>>>();
    prep_feats_kernel<<<B_ROWS, 256>>>(x, q);
    mlp_mma_kernel<0><<<dim3(H1D / 128, B_ROWS / 128), 256, MLP_SMEM_DYN>>>(b1);
    mlp_mma_kernel<1><<<dim3(H2D / 128, B_ROWS / 128), 256, MLP_SMEM_DYN>>>(b2);
    layer3_kernel<<<B_ROWS / 8, 256>>>(W3, b3, out);
}